// round 12
// baseline (speedup 1.0000x reference)
#include <cuda_runtime.h>

#define N_NODES 100000
#define N_EDGES 3200000
#define IN_CH   64
#define OUT_C   25
#define W_ELEMS (2 * IN_CH * OUT_C)   // 3200
#define YPAD    32   // y rows padded to 32 floats = 128 B aligned line

// Scratch: y_top at [n*YPAD], y_bot at [(N_NODES+n)*YPAD]. 25.6 MB static,
// zero-initialized: pad cols (25..31) stay 0 forever (lanes 25..31 read them).
__device__ __align__(128) float g_y[2u * N_NODES * YPAD];

__device__ __forceinline__ float tanh_approx(float x) {
    float y;
    asm("tanh.approx.f32 %0, %1;" : "=f"(y) : "f"(x));
    return y;
}

// Deterministic buffer sniff: index data has EVERY 32-bit word < 0x20000
// (indices < 100000; int64 high words are 0). fp32 N(0,1) fails word 0 with
// probability ~1. Fixed addresses -> block-uniform, graph-safe.
__device__ __forceinline__ bool looks_like_indices(const void* p) {
    const unsigned* u = (const unsigned*)p;
    bool small = true;
#pragma unroll
    for (int i = 0; i < 64; ++i) small &= (__ldg(u + i) < 0x20000u);
    return small;
}

// Packed f32x2 FMA (sm_103a): d = a * b + d on two fp32 lanes.
__device__ __forceinline__ void fma2(unsigned long long& d,
                                     unsigned long long a, unsigned long long b) {
    asm("fma.rn.f32x2 %0, %1, %2, %0;" : "+l"(d) : "l"(a), "l"(b));
}

// ---------------------------------------------------------------------------
// Kernel 1: per-node precompute, TWO sequential half-passes (top then bottom)
// to cap live accumulators at 14 u64 regs (~60 regs total, no spill risk).
// W in smem as [64][56]: cols 0..27 = W_top (25+3 zeros), 28..55 = W_bot.
// ---------------------------------------------------------------------------
__global__ void __launch_bounds__(128) precompute_kernel(const void* __restrict__ pA,
                                                         const void* __restrict__ pB,
                                                         const float* __restrict__ W) {
    const float* x = looks_like_indices(pA) ? (const float*)pB : (const float*)pA;

    __shared__ __align__(16) float ws[64 * 56];
    for (int i = threadIdx.x; i < 64 * 56; i += 128) {
        int k = i / 56, c = i % 56;
        float v = 0.0f;
        if (c < 28) {
            if (c < 25) v = W[k * 25 + c];
        } else {
            int cc = c - 28;
            if (cc < 25) v = W[(64 + k) * 25 + cc];
        }
        ws[i] = v;
    }
    __syncthreads();

    int n = blockIdx.x * 128 + threadIdx.x;
    if (n >= N_NODES) return;

    const float4* xr = (const float4*)(x + (size_t)n * IN_CH);

#pragma unroll
    for (int half = 0; half < 2; ++half) {
        unsigned long long acc[14];   // 28 floats
#pragma unroll
        for (int i = 0; i < 14; ++i) acc[i] = 0ull;

        const int woff = half * 28;   // column offset into ws rows
#pragma unroll 2
        for (int k4 = 0; k4 < 16; ++k4) {
            float4 xv = __ldg(xr + k4);
#pragma unroll
            for (int kk = 0; kk < 4; ++kk) {
                float xs = (kk == 0) ? xv.x : (kk == 1) ? xv.y : (kk == 2) ? xv.z : xv.w;
                unsigned long long x2;
                asm("mov.b64 %0, {%1, %1};" : "=l"(x2) : "f"(xs));
                const ulonglong2* wrow =
                    (const ulonglong2*)(ws + (k4 * 4 + kk) * 56 + woff);
#pragma unroll
                for (int c = 0; c < 7; ++c) {
                    ulonglong2 w = wrow[c];        // LDS.128 broadcast
                    fma2(acc[2 * c],     x2, w.x);
                    fma2(acc[2 * c + 1], x2, w.y);
                }
            }
        }

        float* yrow = g_y + ((size_t)half * N_NODES + n) * YPAD;
#pragma unroll
        for (int i = 0; i < 7; ++i)
            __stcg((ulonglong2*)yrow + i, make_ulonglong2(acc[2 * i], acc[2 * i + 1]));
    }
}

// ---------------------------------------------------------------------------
// Kernel 2: edge pass, warp-per-edge, ZERO smem staging.
// All 32 lanes load one float of the edge's padded y rows (one 128B line per
// gather, lanes 25..31 read the zero pad); lanes 0..24 store directly to out.
// Index loads are warp-uniform broadcasts (L1-hot).
// ---------------------------------------------------------------------------
__global__ void __launch_bounds__(256) edge_kernel(const void* __restrict__ pA,
                                                   const void* __restrict__ pB,
                                                   float* __restrict__ out) {
    const void* ei_raw = looks_like_indices(pA) ? pA : pB;
    const int*  ei32   = (const int*)ei_raw;

    // dtype sniff: int64 indices -> every odd 32-bit word is zero.
    bool is64 = true;
#pragma unroll
    for (int i = 1; i < 64; i += 2) is64 &= (__ldg((const unsigned*)ei_raw + i) == 0u);

    const int lane  = threadIdx.x & 31;
    const int warp  = threadIdx.x >> 5;
    const int ebase = blockIdx.x * 256 + warp * 32;   // 32 edges per warp

    const float* ytop = g_y;
    const float* ybot = g_y + (size_t)N_NODES * YPAD;

    if (is64) {
#pragma unroll 4
        for (int it = 0; it < 32; ++it) {
            int e = ebase + it;
            int r = __ldg(ei32 + 2 * e);                    // low word (uniform)
            int c = __ldg(ei32 + 2 * (N_EDGES + e));
            r = min(max(r, 0), N_NODES - 1);
            c = min(max(c, 0), N_NODES - 1);
            float a = __ldg(ytop + r * YPAD + lane);        // one 128B line
            float b = __ldg(ybot + c * YPAD + lane);
            float v = tanh_approx(a + b);
            if (lane < OUT_C) out[(size_t)e * OUT_C + lane] = v;
        }
    } else {
#pragma unroll 4
        for (int it = 0; it < 32; ++it) {
            int e = ebase + it;
            int r = __ldg(ei32 + e);
            int c = __ldg(ei32 + N_EDGES + e);
            r = min(max(r, 0), N_NODES - 1);
            c = min(max(c, 0), N_NODES - 1);
            float a = __ldg(ytop + r * YPAD + lane);
            float b = __ldg(ybot + c * YPAD + lane);
            float v = tanh_approx(a + b);
            if (lane < OUT_C) out[(size_t)e * OUT_C + lane] = v;
        }
    }
}

// ---------------------------------------------------------------------------
extern "C" void kernel_launch(void* const* d_in, const int* in_sizes, int n_in,
                              void* d_out, int out_size) {
    // W is the unique size-3200 input. x and edge_index have IDENTICAL element
    // counts (6.4M); those two are disambiguated on-device by content sniff.
    int wi = 0;
    for (int i = 0; i < n_in; ++i)
        if (in_sizes[i] == W_ELEMS) wi = i;
    int ai = (wi == 0) ? 1 : 0;
    int bi = (wi == 2) ? 1 : 2;

    const void*  pA  = d_in[ai];
    const void*  pB  = d_in[bi];
    const float* W   = (const float*)d_in[wi];
    float*       out = (float*)d_out;

    precompute_kernel<<<(N_NODES + 127) / 128, 128>>>(pA, pB, W);
    edge_kernel<<<N_EDGES / 256, 256>>>(pA, pB, out);
}